// round 7
// baseline (speedup 1.0000x reference)
#include <cuda_runtime.h>
#include <cuda_fp16.h>
#include <cstdint>

#define PV   113
#define PVP  128
#define DIM  128
#define NH   4
#define DHD  32
#define HID  512
#define NCOMBO 226
#define NCOMBOP 228
#define NPAIR (PV*PV)      // 12769
#define NTOK  (NPAIR*2)    // 25538
#define PPB   64           // pairs per GEMM CTA (128 rows)
#define KCH   64
#define NCHUNK (HID/KCH)   // 8
#define GEMM_GRID ((NPAIR + PPB - 1)/PPB)   // 200

// ---------------- device scratch (zero-initialized) ----------------
__device__ __align__(16) float g_OW1[NH*DHD*HID];
__device__ __align__(16) float g_OU [NH*DHD*PV];
__device__ __align__(16) float g_b2u[PV];
__device__ __align__(16) float g_qk [2*NCOMBO*DIM + 4*DIM];
__device__ __align__(16) float g_EW1[NCOMBOP*HID];            // fp32, padded
__device__ __align__(16) float g_EU [NCOMBOP*PVP];            // fp32, stride 128
__device__ __align__(16) float g_AW1[NCOMBOP*NH*HID];         // fp32, a-side use
__device__ __align__(16) float g_Ec [NCHUNK*NCOMBOP*64];      // chunk-major EW1
__device__ __align__(16) __half g_Ac [NCHUNK*NCOMBOP*256];    // chunk-major AW1 fp16
__device__ __align__(16) __half g_AUh[NCOMBOP*NH*PVP];        // AU fp16 [combo][4][128]
__device__ __align__(16) __half g_Bh[HID*DIM];                // [k][n] W2U fp16
__device__ __align__(16) float g_table[(size_t)NTOK*PV];

// ---------------- helpers ----------------
__device__ __forceinline__ uint32_t smem_u32(const void* p){
    uint32_t a;
    asm("{ .reg .u64 t; cvta.to.shared.u64 t, %1; cvt.u32.u64 %0, t; }" : "=r"(a) : "l"(p));
    return a;
}
__device__ __forceinline__ void cpa16(uint32_t dst, const void* src){
    asm volatile("cp.async.cg.shared.global [%0], [%1], 16;" :: "r"(dst), "l"(src));
}
__device__ __forceinline__ void cpa_commit(){ asm volatile("cp.async.commit_group;"); }
__device__ __forceinline__ void ldsm4(uint32_t* r, uint32_t a){
    asm volatile("ldmatrix.sync.aligned.m8n8.x4.shared.b16 {%0,%1,%2,%3}, [%4];"
        : "=r"(r[0]),"=r"(r[1]),"=r"(r[2]),"=r"(r[3]) : "r"(a));
}
__device__ __forceinline__ void ldsm4t(uint32_t* r, uint32_t a){
    asm volatile("ldmatrix.sync.aligned.m8n8.x4.trans.shared.b16 {%0,%1,%2,%3}, [%4];"
        : "=r"(r[0]),"=r"(r[1]),"=r"(r[2]),"=r"(r[3]) : "r"(a));
}
__device__ __forceinline__ void mma16816(float* c, const uint32_t* a, uint32_t b0, uint32_t b1){
    asm volatile("mma.sync.aligned.m16n8k16.row.col.f32.f16.f16.f32 "
        "{%0,%1,%2,%3}, {%4,%5,%6,%7}, {%8,%9}, {%0,%1,%2,%3};"
        : "+f"(c[0]),"+f"(c[1]),"+f"(c[2]),"+f"(c[3])
        : "r"(a[0]),"r"(a[1]),"r"(a[2]),"r"(a[3]), "r"(b0),"r"(b1));
}
__device__ __forceinline__ int permA(int m){ int t = m & 7; return (t>>1) | ((t&1)<<2); }

// ---------------- A1: fold weights ----------------
__global__ void kA1(const float* __restrict__ WO, const float* __restrict__ W1,
                    const float* __restrict__ W2, const float* __restrict__ b2,
                    const float* __restrict__ WU){
    int t = blockIdx.x*256 + threadIdx.x;
    if (t < 65536) {
        int j = t & 511, hi = t >> 9;
        const float* wo = WO + hi*DIM;
        float s = 0.f;
        #pragma unroll 8
        for (int d=0; d<DIM; d++) s += wo[d]*W1[d*HID + j];
        g_OW1[t] = s;
    } else if (t < 80000) {
        int u = t - 65536; int p = u % PV; int hi = u / PV;
        const float* wo = WO + hi*DIM; const float* wu = WU + p*DIM;
        float s = 0.f;
        #pragma unroll 8
        for (int d=0; d<DIM; d++) s += wo[d]*wu[d];
        g_OU[u] = s;
    } else if (t < 145536) {
        int u = t - 80000; int n = u & 127; int j = u >> 7;
        float s = 0.f;
        if (n < PV) {
            const float* w2 = W2 + j*DIM; const float* wu = WU + n*DIM;
            #pragma unroll 8
            for (int d=0; d<DIM; d++) s += w2[d]*wu[d];
        }
        g_Bh[u] = __float2half_rn(s);
    } else if (t < 145649) {
        int p = t - 145536;
        const float* wu = WU + p*DIM;
        float s = 0.f;
        #pragma unroll 8
        for (int d=0; d<DIM; d++) s += b2[d]*wu[d];
        g_b2u[p] = s;
    }
}

// ---------------- A2: per-combo tables (+ chunk-major copies) ----------------
__global__ void kA2(const float* __restrict__ tok_emb, const float* __restrict__ pos_emb,
                    const float* __restrict__ WQ, const float* __restrict__ WK,
                    const float* __restrict__ WV, const float* __restrict__ W1,
                    const float* __restrict__ b1, const float* __restrict__ WU){
    __shared__ float e[DIM];
    __shared__ float vv[DIM];
    const int c = blockIdx.x;
    const int tk = c >> 1, pos = c & 1;
    const int tid = threadIdx.x;
    if (tid < DIM) e[tid] = tok_emb[tk*DIM + tid] + pos_emb[pos*DIM + tid];
    __syncthreads();

    for (int o = tid; o < 384; o += 256) {
        int sel = o >> 7; int idx = o & 127;
        const float* W = (sel==0) ? WQ : ((sel==1) ? WK : WV);
        int h = idx >> 5, i = idx & 31;
        float s = 0.f;
        #pragma unroll 8
        for (int d=0; d<DIM; d++) s += e[d]*W[(h*DIM + d)*DHD + i];
        if (sel < 2) g_qk[(sel*NCOMBO + c)*DIM + idx] = s;
        else         vv[idx] = s;
    }
    __syncthreads();

    for (int j = tid; j < HID; j += 256) {
        float s = b1[j];
        #pragma unroll 8
        for (int d=0; d<DIM; d++) s += e[d]*W1[d*HID + j];
        g_EW1[c*HID + j] = s;
        g_Ec[((j>>6)*NCOMBOP + c)*64 + (j&63)] = s;
    }
    if (tid < PV) {
        const float* wu = WU + tid*DIM;
        float s = g_b2u[tid];
        #pragma unroll 8
        for (int d=0; d<DIM; d++) s += e[d]*wu[d];
        g_EU[c*PVP + tid] = s;
    }
    for (int o = tid; o < NH*HID; o += 256) {
        int h = o >> 9; int j = o & 511;
        float s = 0.f;
        #pragma unroll
        for (int i=0; i<DHD; i++) s += vv[h*DHD + i]*g_OW1[(h*DHD + i)*HID + j];
        g_AW1[(c*NH + h)*HID + j] = s;
        g_Ac[((j>>6)*NCOMBOP + c)*256 + h*64 + (j&63)] = __float2half_rn(s);
    }
    for (int o = tid; o < NH*PV; o += 256) {
        int h = o / PV; int p = o % PV;
        float s = 0.f;
        #pragma unroll
        for (int i=0; i<DHD; i++) s += vv[h*DHD + i]*g_OU[(h*DHD + i)*PV + p];
        g_AUh[(c*NH + h)*PVP + p] = __float2half_rn(s);
    }
}

// ---------------- kFB7: fully-staged fused kernel ----------------
#define SM_PAT   0
#define SM_CBI   4096
#define SM_ASIDE 4608
#define SM_ATILE 25088
#define SM_BTILE 41472
#define SM_EC    74240
#define SM_AC    109056
#define SMEM_TOT 176640
#define EC_STRIDE 272
#define AC_STRIDE 528

__device__ __forceinline__ uint4 packrow_h(const float* pr){
    uint32_t w[4];
    #pragma unroll
    for (int i=0;i<4;i++){
        __half h0 = __float2half_rn(fmaxf(pr[2*i],   0.f));
        __half h1 = __float2half_rn(fmaxf(pr[2*i+1], 0.f));
        w[i] = (uint32_t)__half_as_ushort(h0) | ((uint32_t)__half_as_ushort(h1) << 16);
    }
    return make_uint4(w[0],w[1],w[2],w[3]);
}

__global__ void __launch_bounds__(512, 1) kFB7(){
    extern __shared__ char smem[];
    float* sPat = (float*)smem;
    int*   sCb  = (int*)(smem + SM_CBI);
    float* sAside = (float*)(smem + SM_ASIDE);
    const uint32_t sb = smem_u32(smem);
    const int tid = threadIdx.x, lane = tid & 31, wid = tid >> 5;
    const int wm = wid >> 2, wn = wid & 3;
    const int p0 = blockIdx.x * PPB;
    const int a0g = p0 / PV, a1g = (p0 + PPB - 1) / PV;

    if (tid < 64) sCb[tid] = 2*((p0 + tid) % PV) + 1;
    __syncthreads();

    // ---------- staging lambda ----------
    auto stage = [&](int c){
        const int buf = c & 1;
        const uint32_t aB  = sb + SM_BTILE + buf*16384;
        const uint32_t aEc = sb + SM_EC + buf*17408;
        const uint32_t aAc = sb + SM_AC + buf*33792;
        const int kk = c*KCH;
        #pragma unroll
        for (int i=0;i<2;i++){
            int lin = tid + i*512;           // Btile: 1024
            int k = lin >> 4, nq = lin & 15;
            cpa16(aB + k*256 + ((nq ^ (k & 7)) << 4), g_Bh + (kk+k)*DIM + nq*8);
        }
        #pragma unroll
        for (int i=0;i<2;i++){
            int lin = tid + i*512;           // Ec: 1024
            int cmb = lin >> 4, quad = lin & 15;
            cpa16(aEc + cmb*EC_STRIDE + quad*16,
                  g_Ec + (c*NCOMBOP + sCb[cmb])*64 + quad*4);
        }
        #pragma unroll
        for (int i=0;i<4;i++){
            int lin = tid + i*512;           // Ac: 2048
            int cmb = lin >> 5, quad = lin & 31;
            cpa16(aAc + cmb*AC_STRIDE + quad*16,
                  g_Ac + (c*NCOMBOP + sCb[cmb])*256 + quad*8);
        }
    };

    stage(0); cpa_commit();

    // ---------- attention pattern (512 threads = 64 pairs x 4 heads x 2 qi) ----------
    {
        const float isq = 0.17677669529663687f;
        int pp = tid >> 3;
        int h  = (tid >> 1) & 3;
        int qi = tid & 1;
        int pr = p0 + pp;
        int aa = pr / PV, bb = pr % PV;
        int ca0 = 2*aa, cb0 = 2*bb + 1;
        int cq = qi ? cb0 : ca0;
        const float* q  = g_qk + (0*NCOMBO + cq )*DIM + h*DHD;
        const float* k0 = g_qk + (1*NCOMBO + ca0)*DIM + h*DHD;
        const float* k1 = g_qk + (1*NCOMBO + cb0)*DIM + h*DHD;
        float s0=0.f, s1=0.f;
        #pragma unroll
        for (int i=0;i<DHD;i++){ float qv = q[i]; s0 += qv*k0[i]; s1 += qv*k1[i]; }
        s0 *= isq; s1 *= isq;
        float m = fmaxf(s0, s1);
        float e0 = __expf(s0-m), e1 = __expf(s1-m);
        float p = e0/(e0+e1);
        sPat[pp*16 + h*4 + qi*2 + 0] = 0.5f + 0.5f*p;
        sPat[pp*16 + h*4 + qi*2 + 1] = 0.5f + 0.5f*(1.0f-p);
    }
    // ---------- a-side tables into smem: [2][5][512] fp32 ----------
    for (int idx = tid; idx < 5120; idx += 512){
        int sel = idx / 2560; int rem = idx % 2560;
        int which = rem >> 9; int col = rem & 511;
        int cax = 2*(sel ? a1g : a0g);
        float v = (which == 0) ? g_EW1[cax*HID + col]
                               : g_AW1[(cax*NH + (which-1))*HID + col];
        sAside[idx] = v;
    }
    __syncthreads();

    // per-thread compute state
    const int lp = tid >> 3, q8 = tid & 7;
    const int asel = (((p0 + lp) / PV) != a0g) ? 1 : 0;
    const float* Ea = sAside + asel*2560;
    float pv[16];
    #pragma unroll
    for (int i=0;i<16;i++) pv[i] = sPat[lp*16 + i];

    float acc[2][4][4];
    #pragma unroll
    for (int i=0;i<2;i++)
        #pragma unroll
        for (int j=0;j<4;j++)
            #pragma unroll
            for (int k=0;k<4;k++) acc[i][j][k] = 0.f;

    // ---------- main loop ----------
    for (int c = 0; c < NCHUNK; c++){
        if (c + 1 < NCHUNK){ stage(c + 1); cpa_commit(); }
        if (c + 1 < NCHUNK) asm volatile("cp.async.wait_group 1;");
        else                asm volatile("cp.async.wait_group 0;");
        __syncthreads();

        // ---- compute A tile from smem ----
        {
            const int buf = c & 1;
            const int kk = c*KCH;
            const float*  Eb = (const float*)(smem + SM_EC + buf*17408 + lp*EC_STRIDE);
            const __half* Ab = (const __half*)(smem + SM_AC + buf*33792 + lp*AC_STRIDE);
            char* pA = smem + SM_ATILE;
            const int j0 = q8*8;
            float4 ea0 = *(const float4*)(Ea + kk + j0);
            float4 ea1 = *(const float4*)(Ea + kk + j0 + 4);
            float4 eb0 = *(const float4*)(Eb + j0);
            float4 eb1 = *(const float4*)(Eb + j0 + 4);
            float pr0[8] = {ea0.x,ea0.y,ea0.z,ea0.w,ea1.x,ea1.y,ea1.z,ea1.w};
            float pr1[8] = {eb0.x,eb0.y,eb0.z,eb0.w,eb1.x,eb1.y,eb1.z,eb1.w};
            #pragma unroll
            for (int h=0; h<NH; h++){
                float4 A0 = *(const float4*)(Ea + 512 + h*512 + kk + j0);
                float4 A1 = *(const float4*)(Ea + 512 + h*512 + kk + j0 + 4);
                uint4 abx = *(const uint4*)(Ab + h*64 + j0);
                float2 b01 = __half22float2(*(__half2*)&abx.x);
                float2 b23 = __half22float2(*(__half2*)&abx.y);
                float2 b45 = __half22float2(*(__half2*)&abx.z);
                float2 b67 = __half22float2(*(__half2*)&abx.w);
                float aa[8] = {A0.x,A0.y,A0.z,A0.w,A1.x,A1.y,A1.z,A1.w};
                float bb[8] = {b01.x,b01.y,b23.x,b23.y,b45.x,b45.y,b67.x,b67.y};
                float w00 = pv[h*4+0], w01 = pv[h*4+1];
                float w10 = pv[h*4+2], w11 = pv[h*4+3];
                #pragma unroll
                for (int cc=0;cc<8;cc++){
                    pr0[cc] += w00*aa[cc] + w01*bb[cc];
                    pr1[cc] += w10*aa[cc] + w11*bb[cc];
                }
            }
            int m0 = 2*lp, m1 = m0 + 1;
            *(uint4*)(pA + m0*128 + ((q8 ^ permA(m0)) << 4)) = packrow_h(pr0);
            *(uint4*)(pA + m1*128 + ((q8 ^ permA(m1)) << 4)) = packrow_h(pr1);
        }
        __syncthreads();

        // ---- MMA ----
        {
            const int buf = c & 1;
            const uint32_t aA = sb + SM_ATILE;
            const uint32_t aB = sb + SM_BTILE + buf*16384;
            #pragma unroll
            for (int ks=0; ks<4; ks++){
                uint32_t ah[2][4];
                #pragma unroll
                for (int mf=0; mf<2; mf++){
                    int r  = wm*32 + mf*16 + (lane & 15);
                    int kq = ks*2 + (lane >> 4);
                    ldsm4(ah[mf], aA + r*128 + ((kq ^ permA(r)) << 4));
                }
                int kr = ks*16 + (lane & 15);
                #pragma unroll
                for (int nb=0; nb<2; nb++){
                    int nq = wn*4 + nb*2 + (lane >> 4);
                    uint32_t bh[4];
                    ldsm4t(bh, aB + kr*256 + ((nq ^ (kr & 7)) << 4));
                    #pragma unroll
                    for (int mf=0; mf<2; mf++){
                        mma16816(acc[mf][nb*2],   ah[mf], bh[0], bh[1]);
                        mma16816(acc[mf][nb*2+1], ah[mf], bh[2], bh[3]);
                    }
                }
            }
        }
        __syncthreads();
    }

    // ---------- stage epilogue tables (reuse braw buffers) ----------
    // EU fp32: 66 rows x 512B at SM_EC; AU fp16: 66 rows x 1024B at SM_AC
    for (int lin = tid; lin < 2112; lin += 512){
        int row = lin >> 5, quad = lin & 31;
        int cmb = (row < 64) ? sCb[row] : ((row == 64) ? 2*a0g : 2*a1g);
        uint32_t dq = (uint32_t)(quad ^ ((row & 7) << 2));
        cpa16(sb + SM_EC + row*512 + (dq << 4), g_EU + cmb*PVP + quad*4);
    }
    for (int lin = tid; lin < 4224; lin += 512){
        int row = lin >> 6, quad = lin & 63;
        int cmb = (row < 64) ? sCb[row] : ((row == 64) ? 2*a0g : 2*a1g);
        uint32_t dq = (uint32_t)(quad ^ ((row & 7) << 3));
        cpa16(sb + SM_AC + row*1024 + (dq << 4), g_AUh + cmb*NH*PVP + quad*8);
    }
    cpa_commit();
    asm volatile("cp.async.wait_group 0;");
    __syncthreads();

    // ---------- epilogue: base from smem + acc -> g_table ----------
    #pragma unroll
    for (int mf=0; mf<2; mf++){
        #pragma unroll
        for (int hh=0; hh<2; hh++){
            int row = wm*32 + mf*16 + (lane >> 2) + hh*8;
            int rlp = row >> 1, qi = row & 1;
            int arow = (((p0 + rlp) / PV) == a0g) ? 64 : 65;
            int eurow = qi ? rlp : arow;
            int gm = p0*2 + row;
            float wA[4], wB[4];
            #pragma unroll
            for (int h=0; h<NH; h++){
                wA[h] = sPat[rlp*16 + h*4 + qi*2 + 0];
                wB[h] = sPat[rlp*16 + h*4 + qi*2 + 1];
            }
            #pragma unroll
            for (int nf=0; nf<4; nf++){
                int n = wn*32 + nf*8 + (lane & 3)*2;
                uint32_t eq = (uint32_t)((n >> 2) ^ ((eurow & 7) << 2));
                float2 base = *(const float2*)(smem + SM_EC + eurow*512 + (eq << 4) + (n & 3)*4);
                #pragma unroll
                for (int h=0; h<NH; h++){
                    int byteo = h*256 + n*2;
                    uint32_t qa = (uint32_t)((byteo >> 4) ^ ((arow & 7) << 3));
                    uint32_t qb = (uint32_t)((byteo >> 4) ^ ((rlp  & 7) << 3));
                    __half2 va = *(const __half2*)(smem + SM_AC + arow*1024 + (qa << 4) + (byteo & 15));
                    __half2 vb = *(const __half2*)(smem + SM_AC + rlp *1024 + (qb << 4) + (byteo & 15));
                    float2 fa = __half22float2(va);
                    float2 fb = __half22float2(vb);
                    base.x += wA[h]*fa.x + wB[h]*fb.x;
                    base.y += wA[h]*fa.y + wB[h]*fb.y;
                }
                if (gm < NTOK){
                    float* ts = g_table + (size_t)gm*PV;
                    float c0 = acc[mf][nf][hh*2+0] + base.x;
                    float c1 = acc[mf][nf][hh*2+1] + base.y;
                    if (n   < PV) ts[n]   = c0;
                    if (n+1 < PV) ts[n+1] = c1;
                }
            }
        }
    }
}

// ---------------- G: gather ----------------
__global__ void kG(const int* __restrict__ x, float* __restrict__ out, int B){
    int ex = blockIdx.x*8 + (threadIdx.x >> 5);
    if (ex >= B) return;
    int lane = threadIdx.x & 31;
    int a = x[ex*2], b = x[ex*2+1];
    const float2* src = (const float2*)(g_table + (size_t)(a*PV + b)*226);
    float2* dst = (float2*)(out + (size_t)ex*226);
    #pragma unroll
    for (int i=0;i<4;i++){
        int idx = lane + i*32;
        if (idx < PV) dst[idx] = src[idx];
    }
}

// ---------------- launch ----------------
extern "C" void kernel_launch(void* const* d_in, const int* in_sizes, int n_in,
                              void* d_out, int out_size){
    const int*   x   = (const int*)  d_in[0];
    const float* tok = (const float*)d_in[1];
    const float* pos = (const float*)d_in[2];
    const float* WQ  = (const float*)d_in[3];
    const float* WK  = (const float*)d_in[4];
    const float* WV  = (const float*)d_in[5];
    const float* WO  = (const float*)d_in[6];
    const float* W1  = (const float*)d_in[7];
    const float* b1  = (const float*)d_in[8];
    const float* W2  = (const float*)d_in[9];
    const float* b2  = (const float*)d_in[10];
    const float* WU  = (const float*)d_in[11];
    float* out = (float*)d_out;
    const int B = in_sizes[0] / 2;

    cudaFuncSetAttribute(kFB7, cudaFuncAttributeMaxDynamicSharedMemorySize, SMEM_TOT);

    kA1<<<569, 256>>>(WO, W1, W2, b2, WU);
    kA2<<<NCOMBO, 256>>>(tok, pos, WQ, WK, WV, W1, b1, WU);
    kFB7<<<GEMM_GRID, 512, SMEM_TOT>>>();
    kG<<<(B + 7)/8, 256>>>(x, out, B);
}

// round 8
// speedup vs baseline: 1.0804x; 1.0804x over previous
#include <cuda_runtime.h>
#include <cuda_fp16.h>
#include <cstdint>

#define PV   113
#define PVP  128
#define DIM  128
#define NH   4
#define DHD  32
#define HID  512
#define NCOMBO 226
#define NCOMBOP 228
#define NPAIR (PV*PV)      // 12769
#define NTOK  (NPAIR*2)    // 25538
#define PPB   32           // pairs per CTA (64 rows)
#define KCH   64
#define NCHUNK 8
#define GEMM_GRID ((NPAIR + PPB - 1)/PPB)   // 400

// ---------------- device scratch (zero-initialized) ----------------
__device__ __align__(16) float g_OW1[NH*DHD*HID];
__device__ __align__(16) float g_OU [NH*DHD*PV];
__device__ __align__(16) float g_b2u[PV];
__device__ __align__(16) float g_qk [2*NCOMBO*DIM + 4*DIM];
__device__ __align__(16) float g_EU [NCOMBOP*PVP];              // fp32
__device__ __align__(16) __half g_AUh[NCOMBOP*NH*PVP];          // fp16
__device__ __align__(16) __half g_Acz[NCHUNK*NCOMBOP*5*64];     // [chunk][combo][slot0=E,1..4=A][64]
__device__ __align__(16) __half g_Bh[HID*DIM];                  // [k][n] W2U fp16
__device__ __align__(16) float g_table[(size_t)NTOK*PV];

// ---------------- helpers ----------------
__device__ __forceinline__ uint32_t smem_u32(const void* p){
    uint32_t a;
    asm("{ .reg .u64 t; cvta.to.shared.u64 t, %1; cvt.u32.u64 %0, t; }" : "=r"(a) : "l"(p));
    return a;
}
__device__ __forceinline__ void cpa16(uint32_t dst, const void* src){
    asm volatile("cp.async.cg.shared.global [%0], [%1], 16;" :: "r"(dst), "l"(src));
}
__device__ __forceinline__ void cpa_commit(){ asm volatile("cp.async.commit_group;"); }
__device__ __forceinline__ void cpa_wait0(){ asm volatile("cp.async.wait_group 0;"); }
__device__ __forceinline__ void ldsm4(uint32_t* r, uint32_t a){
    asm volatile("ldmatrix.sync.aligned.m8n8.x4.shared.b16 {%0,%1,%2,%3}, [%4];"
        : "=r"(r[0]),"=r"(r[1]),"=r"(r[2]),"=r"(r[3]) : "r"(a));
}
__device__ __forceinline__ void ldsm4t(uint32_t* r, uint32_t a){
    asm volatile("ldmatrix.sync.aligned.m8n8.x4.trans.shared.b16 {%0,%1,%2,%3}, [%4];"
        : "=r"(r[0]),"=r"(r[1]),"=r"(r[2]),"=r"(r[3]) : "r"(a));
}
__device__ __forceinline__ void mma16816(float* c, const uint32_t* a, uint32_t b0, uint32_t b1){
    asm volatile("mma.sync.aligned.m16n8k16.row.col.f32.f16.f16.f32 "
        "{%0,%1,%2,%3}, {%4,%5,%6,%7}, {%8,%9}, {%0,%1,%2,%3};"
        : "+f"(c[0]),"+f"(c[1]),"+f"(c[2]),"+f"(c[3])
        : "r"(a[0]),"r"(a[1]),"r"(a[2]),"r"(a[3]), "r"(b0),"r"(b1));
}
__device__ __forceinline__ int permA(int m){ int t = m & 7; return (t>>1) | ((t&1)<<2); }

// ---------------- A1a: OW1 / OU / b2u ----------------
__global__ void kA1a(const float* __restrict__ WO, const float* __restrict__ W1,
                     const float* __restrict__ b2, const float* __restrict__ WU){
    int t = blockIdx.x*256 + threadIdx.x;
    if (t < 65536) {
        int j = t & 511, hi = t >> 9;
        const float* wo = WO + hi*DIM;
        float s = 0.f;
        #pragma unroll 8
        for (int d=0; d<DIM; d++) s += wo[d]*W1[d*HID + j];
        g_OW1[t] = s;
    } else if (t < 80000) {
        int u = t - 65536; int p = u % PV; int hi = u / PV;
        const float* wo = WO + hi*DIM; const float* wu = WU + p*DIM;
        float s = 0.f;
        #pragma unroll 8
        for (int d=0; d<DIM; d++) s += wo[d]*wu[d];
        g_OU[u] = s;
    } else if (t < 80113) {
        int p = t - 80000;
        const float* wu = WU + p*DIM;
        float s = 0.f;
        #pragma unroll 8
        for (int d=0; d<DIM; d++) s += b2[d]*wu[d];
        g_b2u[p] = s;
    }
}

// ---------------- A1b: Bh = fp16(W2 @ WU^T), [k][n] ----------------
__global__ void kA1b(const float* __restrict__ W2, const float* __restrict__ WU){
    int t = blockIdx.x*256 + threadIdx.x;   // 65536
    int n = t & 127, j = t >> 7;
    float s = 0.f;
    if (n < PV) {
        const float* w2 = W2 + j*DIM; const float* wu = WU + n*DIM;
        #pragma unroll 8
        for (int d=0; d<DIM; d++) s += w2[d]*wu[d];
    }
    g_Bh[t] = __float2half_rn(s);
}

// ---------------- A2: per-combo tables ----------------
__global__ void kA2(const float* __restrict__ tok_emb, const float* __restrict__ pos_emb,
                    const float* __restrict__ WQ, const float* __restrict__ WK,
                    const float* __restrict__ WV, const float* __restrict__ W1,
                    const float* __restrict__ b1, const float* __restrict__ WU){
    __shared__ float e[DIM];
    __shared__ float vv[DIM];
    const int c = blockIdx.x;
    const int tk = c >> 1, pos = c & 1;
    const int tid = threadIdx.x;
    if (tid < DIM) e[tid] = tok_emb[tk*DIM + tid] + pos_emb[pos*DIM + tid];
    __syncthreads();

    for (int o = tid; o < 384; o += 256) {
        int sel = o >> 7; int idx = o & 127;
        const float* W = (sel==0) ? WQ : ((sel==1) ? WK : WV);
        int h = idx >> 5, i = idx & 31;
        float s = 0.f;
        #pragma unroll 8
        for (int d=0; d<DIM; d++) s += e[d]*W[(h*DIM + d)*DHD + i];
        if (sel < 2) g_qk[(sel*NCOMBO + c)*DIM + idx] = s;
        else         vv[idx] = s;
    }
    __syncthreads();

    // EW1 -> Acz slot 0
    for (int j = tid; j < HID; j += 256) {
        float s = b1[j];
        #pragma unroll 8
        for (int d=0; d<DIM; d++) s += e[d]*W1[d*HID + j];
        g_Acz[(((j>>6)*NCOMBOP + c)*5 + 0)*64 + (j&63)] = __float2half_rn(s);
    }
    // EU (fp32)
    if (tid < PV) {
        const float* wu = WU + tid*DIM;
        float s = g_b2u[tid];
        #pragma unroll 8
        for (int d=0; d<DIM; d++) s += e[d]*wu[d];
        g_EU[c*PVP + tid] = s;
    }
    // AW1 -> Acz slots 1..4
    for (int o = tid; o < NH*HID; o += 256) {
        int h = o >> 9; int j = o & 511;
        float s = 0.f;
        #pragma unroll
        for (int i=0; i<DHD; i++) s += vv[h*DHD + i]*g_OW1[(h*DHD + i)*HID + j];
        g_Acz[(((j>>6)*NCOMBOP + c)*5 + 1 + h)*64 + (j&63)] = __float2half_rn(s);
    }
    // AU fp16
    for (int o = tid; o < NH*PV; o += 256) {
        int h = o / PV; int p = o % PV;
        float s = 0.f;
        #pragma unroll
        for (int i=0; i<DHD; i++) s += vv[h*DHD + i]*g_OU[(h*DHD + i)*PV + p];
        g_AUh[(c*NH + h)*PVP + p] = __float2half_rn(s);
    }
}

// ---------------- kFB8: M=64 fused kernel, 3 CTAs/SM ----------------
#define SM_PAT   0        // 32*16*4 = 2048
#define SM_CMB   2048     // 34 ints
#define SM_ATILE 2560     // 64*128 = 8192
#define SM_ACZ   10752    // 34 rows * 656B = 22304
#define SM_B     33280    // 2 * 16384
#define SMEM_TOT 66048
#define ACZ_STR  656

__global__ void __launch_bounds__(256, 3) kFB8(){
    extern __shared__ char smem[];
    float* sPat = (float*)smem;
    int*   sCmb = (int*)(smem + SM_CMB);
    const uint32_t sb = smem_u32(smem);
    const int tid = threadIdx.x, lane = tid & 31, wid = tid >> 5;
    const int wm = wid >> 2, wn = wid & 3;          // 2 x 4 warp grid
    const int p0 = blockIdx.x * PPB;
    const int a0g = p0 / PV;

    if (tid < 32) {
        int pr = min(p0 + tid, NPAIR-1);
        sCmb[tid] = 2*(pr % PV) + 1;
    } else if (tid == 32) sCmb[32] = 2*a0g;
    else if (tid == 33)   sCmb[33] = 2*(min(p0 + PPB - 1, NPAIR-1)/PV);
    __syncthreads();

    // ---------- staging ----------
    auto stage = [&](int c){
        // ACZ: 34 rows x 640B -> 1360 x 16B
        const uint32_t aZ = sb + SM_ACZ;
        for (int i=0;i<6;i++){
            int lin = tid + i*256;
            if (lin < 1360){
                int row = lin / 40, x = lin % 40;
                cpa16(aZ + row*ACZ_STR + x*16,
                      g_Acz + ((size_t)(c*NCOMBOP + sCmb[row]))*320 + x*8);
            }
        }
        // B tile: 1024 x 16B into buf c&1
        const uint32_t aB = sb + SM_B + (c&1)*16384;
        const int kk = c*KCH;
        #pragma unroll
        for (int i=0;i<4;i++){
            int lin = tid + i*256;
            int k = lin >> 4, nq = lin & 15;
            cpa16(aB + k*256 + ((nq ^ (k & 7)) << 4), g_Bh + (kk+k)*DIM + nq*8);
        }
    };

    stage(0); cpa_commit();

    // ---------- pattern: 256 threads = 32 pairs x 4 heads x 2 qi ----------
    {
        const float isq = 0.17677669529663687f;
        int pp = tid >> 3, h = (tid >> 1) & 3, qi = tid & 1;
        int pr = min(p0 + pp, NPAIR-1);
        int aa = pr / PV, bb = pr % PV;
        int ca0 = 2*aa, cb0 = 2*bb + 1;
        int cq = qi ? cb0 : ca0;
        const float* q  = g_qk + (0*NCOMBO + cq )*DIM + h*DHD;
        const float* k0 = g_qk + (1*NCOMBO + ca0)*DIM + h*DHD;
        const float* k1 = g_qk + (1*NCOMBO + cb0)*DIM + h*DHD;
        float s0=0.f, s1=0.f;
        #pragma unroll
        for (int i=0;i<DHD;i++){ float qv = q[i]; s0 += qv*k0[i]; s1 += qv*k1[i]; }
        s0 *= isq; s1 *= isq;
        float m = fmaxf(s0, s1);
        float e0 = __expf(s0-m), e1 = __expf(s1-m);
        float p = e0/(e0+e1);
        sPat[pp*16 + h*4 + qi*2 + 0] = 0.5f + 0.5f*p;
        sPat[pp*16 + h*4 + qi*2 + 1] = 0.5f + 0.5f*(1.0f-p);
    }
    cpa_wait0();
    __syncthreads();

    // per-thread A-compute state: row = tid>>2 (0..63), q16 = tid&3
    const int row = tid >> 2, q16 = tid & 3;
    const int lp = row >> 1, qi = row & 1;
    const int asel = (min(p0 + lp, NPAIR-1)/PV != a0g) ? 1 : 0;
    const uint32_t zb = sb + SM_ACZ + lp*ACZ_STR;
    const uint32_t za = sb + SM_ACZ + (32 + asel)*ACZ_STR;
    float wza[5], wzb[5];
    wza[0] = qi ? 0.f : 1.f;  wzb[0] = qi ? 1.f : 0.f;
    #pragma unroll
    for (int h=0; h<NH; h++){
        wza[1+h] = sPat[lp*16 + h*4 + qi*2 + 0];
        wzb[1+h] = sPat[lp*16 + h*4 + qi*2 + 1];
    }

    float acc[2][4][4];
    #pragma unroll
    for (int i=0;i<2;i++)
        #pragma unroll
        for (int j=0;j<4;j++)
            #pragma unroll
            for (int k=0;k<4;k++) acc[i][j][k] = 0.f;

    // ---------- main loop ----------
    for (int c = 0; c < NCHUNK; c++){
        // ---- compute A(c) from ACZ ----
        #pragma unroll
        for (int g=0; g<2; g++){
            const int boff = q16*32 + g*16;      // byte offset within 128B slot row
            float pr8[8] = {0,0,0,0,0,0,0,0};
            #pragma unroll
            for (int s=0; s<5; s++){
                uint4 va = *(const uint4*)(smem + (za - sb) + s*128 + boff);
                uint4 vb = *(const uint4*)(smem + (zb - sb) + s*128 + boff);
                float2 a0 = __half22float2(*(__half2*)&va.x);
                float2 a1 = __half22float2(*(__half2*)&va.y);
                float2 a2 = __half22float2(*(__half2*)&va.z);
                float2 a3 = __half22float2(*(__half2*)&va.w);
                float2 b0 = __half22float2(*(__half2*)&vb.x);
                float2 b1 = __half22float2(*(__half2*)&vb.y);
                float2 b2 = __half22float2(*(__half2*)&vb.z);
                float2 b3 = __half22float2(*(__half2*)&vb.w);
                float wa = wza[s], wb = wzb[s];
                pr8[0] += wa*a0.x + wb*b0.x;  pr8[1] += wa*a0.y + wb*b0.y;
                pr8[2] += wa*a1.x + wb*b1.x;  pr8[3] += wa*a1.y + wb*b1.y;
                pr8[4] += wa*a2.x + wb*b2.x;  pr8[5] += wa*a2.y + wb*b2.y;
                pr8[6] += wa*a3.x + wb*b3.x;  pr8[7] += wa*a3.y + wb*b3.y;
            }
            __half2 h0 = __floats2half2_rn(fmaxf(pr8[0],0.f), fmaxf(pr8[1],0.f));
            __half2 h1 = __floats2half2_rn(fmaxf(pr8[2],0.f), fmaxf(pr8[3],0.f));
            __half2 h2 = __floats2half2_rn(fmaxf(pr8[4],0.f), fmaxf(pr8[5],0.f));
            __half2 h3 = __floats2half2_rn(fmaxf(pr8[6],0.f), fmaxf(pr8[7],0.f));
            int kq = q16*2 + g;
            uint32_t off = (uint32_t)(SM_ATILE + row*128 + ((kq ^ permA(row)) << 4));
            uint4 pk; pk.x = *(uint32_t*)&h0; pk.y = *(uint32_t*)&h1;
                      pk.z = *(uint32_t*)&h2; pk.w = *(uint32_t*)&h3;
            *(uint4*)(smem + off) = pk;
        }
        __syncthreads();                 // Atile ready, ACZ(c) consumed

        if (c + 1 < NCHUNK){ stage(c + 1); cpa_commit(); }

        // ---- MMA(c) ----
        {
            const uint32_t aA = sb + SM_ATILE;
            const uint32_t aB = sb + SM_B + (c&1)*16384;
            #pragma unroll
            for (int ks=0; ks<4; ks++){
                uint32_t ah[2][4];
                #pragma unroll
                for (int mf=0; mf<2; mf++){
                    int r  = wm*32 + mf*16 + (lane & 15);
                    int kq = ks*2 + (lane >> 4);
                    ldsm4(ah[mf], aA + r*128 + ((kq ^ permA(r)) << 4));
                }
                int kr = ks*16 + (lane & 15);
                #pragma unroll
                for (int nb=0; nb<2; nb++){
                    int nq = wn*4 + nb*2 + (lane >> 4);
                    uint32_t bh[4];
                    ldsm4t(bh, aB + kr*256 + ((nq ^ (kr & 7)) << 4));
                    #pragma unroll
                    for (int mf=0; mf<2; mf++){
                        mma16816(acc[mf][nb*2],   ah[mf], bh[0], bh[1]);
                        mma16816(acc[mf][nb*2+1], ah[mf], bh[2], bh[3]);
                    }
                }
            }
        }
        if (c + 1 < NCHUNK) cpa_wait0();
        __syncthreads();                 // Atile/B(c) consumed; next bufs ready
    }

    // ---------- epilogue: base (direct LDG) + acc -> g_table ----------
    #pragma unroll
    for (int mf=0; mf<2; mf++){
        #pragma unroll
        for (int hh=0; hh<2; hh++){
            int r = wm*32 + mf*16 + (lane >> 2) + hh*8;
            int rlp = r >> 1, rqi = r & 1;
            int pair = p0 + rlp;
            int cpair = min(pair, NPAIR-1);
            int ra = cpair / PV, rb = cpair % PV;
            int rca = 2*ra, rcb = 2*rb + 1;
            int cq = rqi ? rcb : rca;
            int gm = pair*2 + rqi;
            float wA[4], wB[4];
            #pragma unroll
            for (int h=0; h<NH; h++){
                wA[h] = sPat[rlp*16 + h*4 + rqi*2 + 0];
                wB[h] = sPat[rlp*16 + h*4 + rqi*2 + 1];
            }
            const float*  eu  = g_EU  + cq*PVP;
            const __half* aua = g_AUh + (rca*NH)*PVP;
            const __half* aub = g_AUh + (rcb*NH)*PVP;
            #pragma unroll
            for (int nf=0; nf<4; nf++){
                int n = wn*32 + nf*8 + (lane & 3)*2;
                float2 base = *(const float2*)(eu + n);
                #pragma unroll
                for (int h=0; h<NH; h++){
                    float2 fa = __half22float2(*(const __half2*)(aua + h*PVP + n));
                    float2 fb = __half22float2(*(const __half2*)(aub + h*PVP + n));
                    base.x += wA[h]*fa.x + wB[h]*fb.x;
                    base.y += wA[h]*fa.y + wB[h]*fb.y;
                }
                if (pair < NPAIR){
                    float* ts = g_table + (size_t)gm*PV;
                    float c0 = acc[mf][nf][hh*2+0] + base.x;
                    float c1 = acc[mf][nf][hh*2+1] + base.y;
                    if (n   < PV) ts[n]   = c0;
                    if (n+1 < PV) ts[n+1] = c1;
                }
            }
        }
    }
}

// ---------------- G: gather ----------------
__global__ void kG(const int* __restrict__ x, float* __restrict__ out, int B){
    int ex = blockIdx.x*8 + (threadIdx.x >> 5);
    if (ex >= B) return;
    int lane = threadIdx.x & 31;
    int a = x[ex*2], b = x[ex*2+1];
    const float2* src = (const float2*)(g_table + (size_t)(a*PV + b)*226);
    float2* dst = (float2*)(out + (size_t)ex*226);
    #pragma unroll
    for (int i=0;i<4;i++){
        int idx = lane + i*32;
        if (idx < PV) dst[idx] = src[idx];
    }
}

// ---------------- launch ----------------
extern "C" void kernel_launch(void* const* d_in, const int* in_sizes, int n_in,
                              void* d_out, int out_size){
    const int*   x   = (const int*)  d_in[0];
    const float* tok = (const float*)d_in[1];
    const float* pos = (const float*)d_in[2];
    const float* WQ  = (const float*)d_in[3];
    const float* WK  = (const float*)d_in[4];
    const float* WV  = (const float*)d_in[5];
    const float* WO  = (const float*)d_in[6];
    const float* W1  = (const float*)d_in[7];
    const float* b1  = (const float*)d_in[8];
    const float* W2  = (const float*)d_in[9];
    const float* b2  = (const float*)d_in[10];
    const float* WU  = (const float*)d_in[11];
    float* out = (float*)d_out;
    const int B = in_sizes[0] / 2;

    cudaFuncSetAttribute(kFB8, cudaFuncAttributeMaxDynamicSharedMemorySize, SMEM_TOT);

    kA1a<<<313, 256>>>(WO, W1, b2, WU);
    kA2<<<NCOMBO, 256>>>(tok, pos, WQ, WK, WV, W1, b1, WU);
    kA1b<<<256, 256>>>(W2, WU);
    kFB8<<<GEMM_GRID, 256, SMEM_TOT>>>();       // 4th launch -> ncu captures this
    kG<<<(B + 7)/8, 256>>>(x, out, B);
}

// round 9
// speedup vs baseline: 1.7398x; 1.6103x over previous
#include <cuda_runtime.h>
#include <cuda_fp16.h>
#include <cstdint>

#define PV   113
#define PVP  128
#define DIM  128
#define NH   4
#define DHD  32
#define HID  512
#define NCOMBO 226
#define NCOMBOP 228
#define NPAIR (PV*PV)      // 12769
#define NTOK  (NPAIR*2)    // 25538
#define PPB   32           // pairs per CTA (64 rows)
#define KCH   64
#define NCHUNK 8
#define GEMM_GRID ((NPAIR + PPB - 1)/PPB)   // 400

// ---------------- device scratch (zero-initialized) ----------------
__device__ __align__(16) float g_E  [256*DIM];                  // embeds, zero-padded rows
__device__ __align__(16) float g_vv [256*DIM];                  // v per combo
__device__ __align__(16) float g_OW1[DIM*HID];
__device__ __align__(16) float g_OU [DIM*PV];
__device__ __align__(16) float g_b2u[PV];
__device__ __align__(16) float g_qk [2*NCOMBO*DIM + 4*DIM];
__device__ __align__(16) float g_EU [NCOMBOP*PVP];              // fp32
__device__ __align__(16) __half g_AUh[NCOMBOP*NH*PVP];          // fp16
__device__ __align__(16) __half g_Acz[NCHUNK*NCOMBOP*5*64];     // [chunk][combo][slot0=E,1..4=A][64]
__device__ __align__(16) __half g_Bh[HID*DIM];                  // [k][n] W2U fp16
__device__ __align__(16) float g_table[(size_t)NTOK*PV];

// ---------------- helpers ----------------
__device__ __forceinline__ uint32_t smem_u32(const void* p){
    uint32_t a;
    asm("{ .reg .u64 t; cvta.to.shared.u64 t, %1; cvt.u32.u64 %0, t; }" : "=r"(a) : "l"(p));
    return a;
}
__device__ __forceinline__ void cpa16(uint32_t dst, const void* src){
    asm volatile("cp.async.cg.shared.global [%0], [%1], 16;" :: "r"(dst), "l"(src));
}
__device__ __forceinline__ void cpa_commit(){ asm volatile("cp.async.commit_group;"); }
__device__ __forceinline__ void cpa_wait0(){ asm volatile("cp.async.wait_group 0;"); }
__device__ __forceinline__ void ldsm4(uint32_t* r, uint32_t a){
    asm volatile("ldmatrix.sync.aligned.m8n8.x4.shared.b16 {%0,%1,%2,%3}, [%4];"
        : "=r"(r[0]),"=r"(r[1]),"=r"(r[2]),"=r"(r[3]) : "r"(a));
}
__device__ __forceinline__ void ldsm4t(uint32_t* r, uint32_t a){
    asm volatile("ldmatrix.sync.aligned.m8n8.x4.trans.shared.b16 {%0,%1,%2,%3}, [%4];"
        : "=r"(r[0]),"=r"(r[1]),"=r"(r[2]),"=r"(r[3]) : "r"(a));
}
__device__ __forceinline__ void mma16816(float* c, const uint32_t* a, uint32_t b0, uint32_t b1){
    asm volatile("mma.sync.aligned.m16n8k16.row.col.f32.f16.f16.f32 "
        "{%0,%1,%2,%3}, {%4,%5,%6,%7}, {%8,%9}, {%0,%1,%2,%3};"
        : "+f"(c[0]),"+f"(c[1]),"+f"(c[2]),"+f"(c[3])
        : "r"(a[0]),"r"(a[1]),"r"(a[2]),"r"(a[3]), "r"(b0),"r"(b1));
}
__device__ __forceinline__ int permA(int m){ int t = m & 7; return (t>>1) | ((t&1)<<2); }

// ---------------- tiled 64x64 GEMM core (K multiple of 32) ----------------
template<class LA, class LB, class LC>
__device__ __forceinline__ void tg64(float (&As)[32][68], float (&Bs)[32][68],
                                     int K, LA la, LB lb, LC lc){
    const int tid = threadIdx.x;
    const int tx = tid & 15, ty = tid >> 4;
    float acc[4][4] = {};
    for (int k0 = 0; k0 < K; k0 += 32){
        {
            int am = tid >> 2, ak = (tid & 3) * 8;
            #pragma unroll
            for (int u=0;u<8;u++) As[ak+u][am] = la(am, k0+ak+u);
        }
        {
            int bk = tid >> 3, bn = (tid & 7) * 8;
            #pragma unroll
            for (int u=0;u<8;u++) Bs[bk][bn+u] = lb(k0+bk, bn+u);
        }
        __syncthreads();
        #pragma unroll
        for (int k=0;k<32;k++){
            float4 a4 = *(const float4*)&As[k][ty*4];
            float4 b4 = *(const float4*)&Bs[k][tx*4];
            float av[4] = {a4.x,a4.y,a4.z,a4.w};
            float bv[4] = {b4.x,b4.y,b4.z,b4.w};
            #pragma unroll
            for (int i=0;i<4;i++)
                #pragma unroll
                for (int j=0;j<4;j++) acc[i][j] += av[i]*bv[j];
        }
        __syncthreads();
    }
    #pragma unroll
    for (int i=0;i<4;i++)
        #pragma unroll
        for (int j=0;j<4;j++) lc(ty*4+i, tx*4+j, acc[i][j]);
}

// ---------------- P0: embeds + b2u ----------------
__global__ void kP0(const float* __restrict__ tok_emb, const float* __restrict__ pos_emb,
                    const float* __restrict__ b2, const float* __restrict__ WU){
    int bid = blockIdx.x, tid = threadIdx.x;
    if (bid < NCOMBO){
        int tk = bid >> 1, pos = bid & 1;
        g_E[bid*DIM + tid] = tok_emb[tk*DIM + tid] + pos_emb[pos*DIM + tid];
    } else {
        if (tid < PV){
            const float* wu = WU + tid*DIM;
            float s = 0.f;
            #pragma unroll 8
            for (int d=0; d<DIM; d++) s += b2[d]*wu[d];
            g_b2u[tid] = s;
        }
    }
}

// ---------------- P1: weight folds + E-side GEMMs ----------------
__global__ void __launch_bounds__(256) kP1(
    const float* __restrict__ WO, const float* __restrict__ W1,
    const float* __restrict__ WQ, const float* __restrict__ WK,
    const float* __restrict__ WV, const float* __restrict__ b1,
    const float* __restrict__ W2, const float* __restrict__ WU){
    __shared__ float As[32][68], Bs[32][68];
    int b = blockIdx.x;
    if (b < 16){                                  // J1: OW1 = WO @ W1  (128x512)
        int l = b; int m0 = (l>>3)*64, n0 = (l&7)*64;
        tg64(As, Bs, 128,
            [&](int m,int k){ return WO[(m0+m)*DIM + k]; },
            [&](int k,int n){ return W1[k*HID + n0+n]; },
            [&](int m,int n,float v){ g_OW1[(m0+m)*HID + n0+n] = v; });
    } else if (b < 20){                           // J2: OU = WO @ WU^T (128x113)
        int l = b-16; int m0 = (l>>1)*64, n0 = (l&1)*64;
        tg64(As, Bs, 128,
            [&](int m,int k){ return WO[(m0+m)*DIM + k]; },
            [&](int k,int n){ int nn=n0+n; return nn<PV ? WU[nn*DIM + k] : 0.f; },
            [&](int m,int n,float v){ int nn=n0+n; if (nn<PV) g_OU[(m0+m)*PV + nn] = v; });
    } else if (b < 36){                           // J3: Bh = fp16(W2 @ WU^T) (512x128)
        int l = b-20; int m0 = (l>>1)*64, n0 = (l&1)*64;
        tg64(As, Bs, 128,
            [&](int m,int k){ return W2[(m0+m)*DIM + k]; },
            [&](int k,int n){ int nn=n0+n; return nn<PV ? WU[nn*DIM + k] : 0.f; },
            [&](int m,int n,float v){ g_Bh[(m0+m)*DIM + n0+n] = __float2half_rn(v); });
    } else if (b < 52){                           // J4: q/k = E @ WQ/WK (226x128)
        int l = b-36; int sel = l >> 3; l &= 7;
        int m0 = (l>>1)*64, n0 = (l&1)*64;
        const float* W = sel ? WK : WQ;
        tg64(As, Bs, 128,
            [&](int m,int k){ return g_E[(m0+m)*DIM + k]; },
            [&](int k,int n){ int nn=n0+n; return W[(nn>>5)*(DIM*DHD) + k*DHD + (nn&31)]; },
            [&](int m,int n,float v){ int c=m0+m; if (c<NCOMBO)
                g_qk[(sel*NCOMBO + c)*DIM + n0+n] = v; });
    } else if (b < 60){                           // J5: vv = E @ WV (226x128)
        int l = b-52; int m0 = (l>>1)*64, n0 = (l&1)*64;
        tg64(As, Bs, 128,
            [&](int m,int k){ return g_E[(m0+m)*DIM + k]; },
            [&](int k,int n){ int nn=n0+n; return WV[(nn>>5)*(DIM*DHD) + k*DHD + (nn&31)]; },
            [&](int m,int n,float v){ g_vv[(m0+m)*DIM + n0+n] = v; });
    } else if (b < 92){                           // J6: EW1 = E @ W1 + b1 -> Acz slot 0
        int l = b-60; int m0 = (l>>3)*64, n0 = (l&7)*64;
        tg64(As, Bs, 128,
            [&](int m,int k){ return g_E[(m0+m)*DIM + k]; },
            [&](int k,int n){ return W1[k*HID + n0+n]; },
            [&](int m,int n,float v){ int c=m0+m, j=n0+n; if (c<NCOMBO)
                g_Acz[(((j>>6)*NCOMBOP + c)*5 + 0)*64 + (j&63)] = __float2half_rn(v + b1[j]); });
    } else {                                      // J7: EU = E @ WU^T + b2u (fp32)
        int l = b-92; int m0 = (l>>1)*64, n0 = (l&1)*64;
        tg64(As, Bs, 128,
            [&](int m,int k){ return g_E[(m0+m)*DIM + k]; },
            [&](int k,int n){ int nn=n0+n; return nn<PV ? WU[nn*DIM + k] : 0.f; },
            [&](int m,int n,float v){ int c=m0+m, nn=n0+n; if (c<NCOMBO)
                g_EU[c*PVP + nn] = v + (nn<PV ? g_b2u[nn] : 0.f); });
    }
}

// ---------------- P2: vv-dependent folds ----------------
__global__ void __launch_bounds__(256) kP2(){
    __shared__ float As[32][68], Bs[32][68];
    int b = blockIdx.x;
    if (b < 128){                                 // J8: AW1[h] = vv_h @ OW1_h -> Acz slot 1+h
        int h = b >> 5; int l = b & 31;
        int m0 = (l>>3)*64, n0 = (l&7)*64;
        tg64(As, Bs, 32,
            [&](int m,int k){ return g_vv[(m0+m)*DIM + h*DHD + k]; },
            [&](int k,int n){ return g_OW1[(h*DHD + k)*HID + n0+n]; },
            [&](int m,int n,float v){ int c=m0+m, j=n0+n; if (c<NCOMBO)
                g_Acz[(((j>>6)*NCOMBOP + c)*5 + 1 + h)*64 + (j&63)] = __float2half_rn(v); });
    } else {                                      // J9: AU[h] = vv_h @ OU_h (fp16)
        int l = b-128; int h = l >> 3; int t = l & 7;
        int m0 = (t>>1)*64, n0 = (t&1)*64;
        tg64(As, Bs, 32,
            [&](int m,int k){ return g_vv[(m0+m)*DIM + h*DHD + k]; },
            [&](int k,int n){ int nn=n0+n; return nn<PV ? g_OU[(h*DHD + k)*PV + nn] : 0.f; },
            [&](int m,int n,float v){ int c=m0+m, nn=n0+n; if (c<NCOMBO && nn<PV)
                g_AUh[(c*NH + h)*PVP + nn] = __float2half_rn(v); });
    }
}

// ---------------- kFB8: M=64 fused kernel, 3 CTAs/SM (unchanged from R8) ----------------
#define SM_PAT   0
#define SM_CMB   2048
#define SM_ATILE 2560
#define SM_ACZ   10752
#define SM_B     33280
#define SMEM_TOT 66048
#define ACZ_STR  656

__global__ void __launch_bounds__(256, 3) kFB8(){
    extern __shared__ char smem[];
    float* sPat = (float*)smem;
    int*   sCmb = (int*)(smem + SM_CMB);
    const uint32_t sb = smem_u32(smem);
    const int tid = threadIdx.x, lane = tid & 31, wid = tid >> 5;
    const int wm = wid >> 2, wn = wid & 3;
    const int p0 = blockIdx.x * PPB;
    const int a0g = p0 / PV;

    if (tid < 32) {
        int pr = min(p0 + tid, NPAIR-1);
        sCmb[tid] = 2*(pr % PV) + 1;
    } else if (tid == 32) sCmb[32] = 2*a0g;
    else if (tid == 33)   sCmb[33] = 2*(min(p0 + PPB - 1, NPAIR-1)/PV);
    __syncthreads();

    auto stage = [&](int c){
        const uint32_t aZ = sb + SM_ACZ;
        for (int i=0;i<6;i++){
            int lin = tid + i*256;
            if (lin < 1360){
                int row = lin / 40, x = lin % 40;
                cpa16(aZ + row*ACZ_STR + x*16,
                      g_Acz + ((size_t)(c*NCOMBOP + sCmb[row]))*320 + x*8);
            }
        }
        const uint32_t aB = sb + SM_B + (c&1)*16384;
        const int kk = c*KCH;
        #pragma unroll
        for (int i=0;i<4;i++){
            int lin = tid + i*256;
            int k = lin >> 4, nq = lin & 15;
            cpa16(aB + k*256 + ((nq ^ (k & 7)) << 4), g_Bh + (kk+k)*DIM + nq*8);
        }
    };

    stage(0); cpa_commit();

    {
        const float isq = 0.17677669529663687f;
        int pp = tid >> 3, h = (tid >> 1) & 3, qi = tid & 1;
        int pr = min(p0 + pp, NPAIR-1);
        int aa = pr / PV, bb = pr % PV;
        int ca0 = 2*aa, cb0 = 2*bb + 1;
        int cq = qi ? cb0 : ca0;
        const float* q  = g_qk + (0*NCOMBO + cq )*DIM + h*DHD;
        const float* k0 = g_qk + (1*NCOMBO + ca0)*DIM + h*DHD;
        const float* k1 = g_qk + (1*NCOMBO + cb0)*DIM + h*DHD;
        float s0=0.f, s1=0.f;
        #pragma unroll
        for (int i=0;i<DHD;i++){ float qv = q[i]; s0 += qv*k0[i]; s1 += qv*k1[i]; }
        s0 *= isq; s1 *= isq;
        float m = fmaxf(s0, s1);
        float e0 = __expf(s0-m), e1 = __expf(s1-m);
        float p = e0/(e0+e1);
        sPat[pp*16 + h*4 + qi*2 + 0] = 0.5f + 0.5f*p;
        sPat[pp*16 + h*4 + qi*2 + 1] = 0.5f + 0.5f*(1.0f-p);
    }
    cpa_wait0();
    __syncthreads();

    const int row = tid >> 2, q16 = tid & 3;
    const int lp = row >> 1, qi = row & 1;
    const int asel = (min(p0 + lp, NPAIR-1)/PV != a0g) ? 1 : 0;
    const uint32_t zb = sb + SM_ACZ + lp*ACZ_STR;
    const uint32_t za = sb + SM_ACZ + (32 + asel)*ACZ_STR;
    float wza[5], wzb[5];
    wza[0] = qi ? 0.f : 1.f;  wzb[0] = qi ? 1.f : 0.f;
    #pragma unroll
    for (int h=0; h<NH; h++){
        wza[1+h] = sPat[lp*16 + h*4 + qi*2 + 0];
        wzb[1+h] = sPat[lp*16 + h*4 + qi*2 + 1];
    }

    float acc[2][4][4];
    #pragma unroll
    for (int i=0;i<2;i++)
        #pragma unroll
        for (int j=0;j<4;j++)
            #pragma unroll
            for (int k=0;k<4;k++) acc[i][j][k] = 0.f;

    for (int c = 0; c < NCHUNK; c++){
        #pragma unroll
        for (int g=0; g<2; g++){
            const int boff = q16*32 + g*16;
            float pr8[8] = {0,0,0,0,0,0,0,0};
            #pragma unroll
            for (int s=0; s<5; s++){
                uint4 va = *(const uint4*)(smem + (za - sb) + s*128 + boff);
                uint4 vb = *(const uint4*)(smem + (zb - sb) + s*128 + boff);
                float2 a0 = __half22float2(*(__half2*)&va.x);
                float2 a1 = __half22float2(*(__half2*)&va.y);
                float2 a2 = __half22float2(*(__half2*)&va.z);
                float2 a3 = __half22float2(*(__half2*)&va.w);
                float2 b0 = __half22float2(*(__half2*)&vb.x);
                float2 b1 = __half22float2(*(__half2*)&vb.y);
                float2 b2 = __half22float2(*(__half2*)&vb.z);
                float2 b3 = __half22float2(*(__half2*)&vb.w);
                float wa = wza[s], wb = wzb[s];
                pr8[0] += wa*a0.x + wb*b0.x;  pr8[1] += wa*a0.y + wb*b0.y;
                pr8[2] += wa*a1.x + wb*b1.x;  pr8[3] += wa*a1.y + wb*b1.y;
                pr8[4] += wa*a2.x + wb*b2.x;  pr8[5] += wa*a2.y + wb*b2.y;
                pr8[6] += wa*a3.x + wb*b3.x;  pr8[7] += wa*a3.y + wb*b3.y;
            }
            __half2 h0 = __floats2half2_rn(fmaxf(pr8[0],0.f), fmaxf(pr8[1],0.f));
            __half2 h1 = __floats2half2_rn(fmaxf(pr8[2],0.f), fmaxf(pr8[3],0.f));
            __half2 h2 = __floats2half2_rn(fmaxf(pr8[4],0.f), fmaxf(pr8[5],0.f));
            __half2 h3 = __floats2half2_rn(fmaxf(pr8[6],0.f), fmaxf(pr8[7],0.f));
            int kq = q16*2 + g;
            uint32_t off = (uint32_t)(SM_ATILE + row*128 + ((kq ^ permA(row)) << 4));
            uint4 pk; pk.x = *(uint32_t*)&h0; pk.y = *(uint32_t*)&h1;
                      pk.z = *(uint32_t*)&h2; pk.w = *(uint32_t*)&h3;
            *(uint4*)(smem + off) = pk;
        }
        __syncthreads();

        if (c + 1 < NCHUNK){ stage(c + 1); cpa_commit(); }

        {
            const uint32_t aA = sb + SM_ATILE;
            const uint32_t aB = sb + SM_B + (c&1)*16384;
            #pragma unroll
            for (int ks=0; ks<4; ks++){
                uint32_t ah[2][4];
                #pragma unroll
                for (int mf=0; mf<2; mf++){
                    int r  = wm*32 + mf*16 + (lane & 15);
                    int kq = ks*2 + (lane >> 4);
                    ldsm4(ah[mf], aA + r*128 + ((kq ^ permA(r)) << 4));
                }
                int kr = ks*16 + (lane & 15);
                #pragma unroll
                for (int nb=0; nb<2; nb++){
                    int nq = wn*4 + nb*2 + (lane >> 4);
                    uint32_t bh[4];
                    ldsm4t(bh, aB + kr*256 + ((nq ^ (kr & 7)) << 4));
                    #pragma unroll
                    for (int mf=0; mf<2; mf++){
                        mma16816(acc[mf][nb*2],   ah[mf], bh[0], bh[1]);
                        mma16816(acc[mf][nb*2+1], ah[mf], bh[2], bh[3]);
                    }
                }
            }
        }
        if (c + 1 < NCHUNK) cpa_wait0();
        __syncthreads();
    }

    #pragma unroll
    for (int mf=0; mf<2; mf++){
        #pragma unroll
        for (int hh=0; hh<2; hh++){
            int r = wm*32 + mf*16 + (lane >> 2) + hh*8;
            int rlp = r >> 1, rqi = r & 1;
            int pair = p0 + rlp;
            int cpair = min(pair, NPAIR-1);
            int ra = cpair / PV, rb = cpair % PV;
            int rca = 2*ra, rcb = 2*rb + 1;
            int cq = rqi ? rcb : rca;
            int gm = pair*2 + rqi;
            float wA[4], wB[4];
            #pragma unroll
            for (int h=0; h<NH; h++){
                wA[h] = sPat[rlp*16 + h*4 + rqi*2 + 0];
                wB[h] = sPat[rlp*16 + h*4 + rqi*2 + 1];
            }
            const float*  eu  = g_EU  + cq*PVP;
            const __half* aua = g_AUh + (rca*NH)*PVP;
            const __half* aub = g_AUh + (rcb*NH)*PVP;
            #pragma unroll
            for (int nf=0; nf<4; nf++){
                int n = wn*32 + nf*8 + (lane & 3)*2;
                float2 base = *(const float2*)(eu + n);
                #pragma unroll
                for (int h=0; h<NH; h++){
                    float2 fa = __half22float2(*(const __half2*)(aua + h*PVP + n));
                    float2 fb = __half22float2(*(const __half2*)(aub + h*PVP + n));
                    base.x += wA[h]*fa.x + wB[h]*fb.x;
                    base.y += wA[h]*fa.y + wB[h]*fb.y;
                }
                if (pair < NPAIR){
                    float* ts = g_table + (size_t)gm*PV;
                    float c0 = acc[mf][nf][hh*2+0] + base.x;
                    float c1 = acc[mf][nf][hh*2+1] + base.y;
                    if (n   < PV) ts[n]   = c0;
                    if (n+1 < PV) ts[n+1] = c1;
                }
            }
        }
    }
}

// ---------------- G: gather ----------------
__global__ void kG(const int* __restrict__ x, float* __restrict__ out, int B){
    int ex = blockIdx.x*8 + (threadIdx.x >> 5);
    if (ex >= B) return;
    int lane = threadIdx.x & 31;
    int a = x[ex*2], b = x[ex*2+1];
    const float2* src = (const float2*)(g_table + (size_t)(a*PV + b)*226);
    float2* dst = (float2*)(out + (size_t)ex*226);
    #pragma unroll
    for (int i=0;i<4;i++){
        int idx = lane + i*32;
        if (idx < PV) dst[idx] = src[idx];
    }
}

// ---------------- launch ----------------
extern "C" void kernel_launch(void* const* d_in, const int* in_sizes, int n_in,
                              void* d_out, int out_size){
    const int*   x   = (const int*)  d_in[0];
    const float* tok = (const float*)d_in[1];
    const float* pos = (const float*)d_in[2];
    const float* WQ  = (const float*)d_in[3];
    const float* WK  = (const float*)d_in[4];
    const float* WV  = (const float*)d_in[5];
    const float* WO  = (const float*)d_in[6];
    const float* W1  = (const float*)d_in[7];
    const float* b1  = (const float*)d_in[8];
    const float* W2  = (const float*)d_in[9];
    const float* b2  = (const float*)d_in[10];
    const float* WU  = (const float*)d_in[11];
    float* out = (float*)d_out;
    const int B = in_sizes[0] / 2;

    cudaFuncSetAttribute(kFB8, cudaFuncAttributeMaxDynamicSharedMemorySize, SMEM_TOT);

    kP0<<<NCOMBO + 1, 128>>>(tok, pos, b2, WU);
    kP1<<<100, 256>>>(WO, W1, WQ, WK, WV, b1, W2, WU);
    kP2<<<160, 256>>>();
    kFB8<<<GEMM_GRID, 256, SMEM_TOT>>>();       // 4th launch -> ncu captures this
    kG<<<(B + 7)/8, 256>>>(x, out, B);
}